// round 7
// baseline (speedup 1.0000x reference)
#include <cuda_runtime.h>

// Heston Monte Carlo: 65536 paths x 512 steps.
// Inputs:  d_in[0] = Z_vol  [65536, 512, 2] f32 (only [:,:,0] used)
//          d_in[1] = Z_price[65536, 512]    f32
// Output:  d_out = S [65536,513] f32 followed by V [65536,513] f32

#define NSTEPS   512
#define NP1      513
#define BATCH    65536
#define TPB      128
#define CHUNK    32
#define NCHUNKS  (NSTEPS / CHUNK)
#define SROW     (CHUNK + 1)   // smem row pitch (pad to kill bank conflicts)

__global__ __launch_bounds__(TPB) void heston_kernel(
    const float2* __restrict__ zvol,    // [BATCH][NSTEPS] float2
    const float*  __restrict__ zprice,  // [BATCH][NSTEPS]
    float* __restrict__ S_out,          // [BATCH][NP1]
    float* __restrict__ V_out)          // [BATCH][NP1]
{
    __shared__ float bufA[TPB * SROW];  // zv tile  -> S tile (in-place)
    __shared__ float bufB[TPB * SROW];  // zp tile  -> V tile (in-place)

    const int tid = threadIdx.x;
    const long long pbase  = (long long)blockIdx.x * TPB;
    const long long mypath = pbase + tid;

    // model constants
    const float dt       = 1.0f / 512.0f;
    const float sqrt_dt  = 0.04419417382415922f;     // sqrt(1/512)
    const float rho      = -0.7f;
    const float rho_perp = 0.7141428428542850f;      // sqrt(0.51)
    const float V0f      = 0.055225f;                 // 0.235^2
    const float kth_dt   = 0.04f * dt;                // KAPPA*THETA*dt (KAPPA=1)
    const float two_sdt  = 2.0f * sqrt_dt;            // SIGMA_V * sqrt_dt

    // t = 0 column (small, uncoalesced, negligible traffic)
    S_out[mypath * NP1] = 100.0f;
    V_out[mypath * NP1] = V0f;

    float V    = V0f;
    float logS = 0.0f;

    float* myA = &bufA[tid * SROW];
    float* myB = &bufB[tid * SROW];

    for (int ck = 0; ck < NCHUNKS; ck++) {
        const int t0 = ck * CHUNK;

        // ---- cooperative coalesced load: each warp reads one path's row chunk ----
        #pragma unroll
        for (int i = tid; i < TPB * CHUNK; i += TPB) {
            const int row = i >> 5;    // path within block
            const int col = i & 31;    // step within chunk
            const long long g = (pbase + row) * (long long)NSTEPS + t0 + col;
            float2 zv2 = zvol[g];                 // 256B/row coalesced, keep .x
            bufA[row * SROW + col] = zv2.x;
            bufB[row * SROW + col] = zprice[g];   // 128B/row coalesced
        }
        __syncthreads();

        // ---- compute: thread owns its path row; overwrite smem with S/V ----
        #pragma unroll
        for (int c = 0; c < CHUNK; c++) {
            const float zv = myA[c];
            const float zp = myB[c];

            const float Vpos = fmaxf(V, 0.0f);
            const float sv   = sqrtf(Vpos);                       // sqrt(V_pos)
            // V_next = V + (theta - Vpos)*dt + 2*sqrt(Vpos*dt)*zv
            float Vnext = fmaf(two_sdt * zv, sv, fmaf(-dt, Vpos, V + kth_dt));
            Vnext = fmaxf(Vnext, 0.0f);

            const float dB = sqrt_dt * fmaf(rho, zv, rho_perp * zp);
            logS = fmaf(sv, dB, fmaf(-0.5f * dt, Vpos, logS));

            myA[c] = 100.0f * __expf(logS);   // S
            myB[c] = Vnext;                   // V
            V = Vnext;
        }
        __syncthreads();

        // ---- cooperative coalesced store ----
        #pragma unroll
        for (int i = tid; i < TPB * CHUNK; i += TPB) {
            const int row = i >> 5;
            const int col = i & 31;
            const long long o = (pbase + row) * (long long)NP1 + (t0 + 1 + col);
            S_out[o] = bufA[row * SROW + col];
            V_out[o] = bufB[row * SROW + col];
        }
        __syncthreads();
    }
}

extern "C" void kernel_launch(void* const* d_in, const int* in_sizes, int n_in,
                              void* d_out, int out_size) {
    const float2* zvol   = (const float2*)d_in[0];
    const float*  zprice = (const float*) d_in[1];
    float* S = (float*)d_out;
    float* Vv = S + (size_t)BATCH * NP1;

    heston_kernel<<<BATCH / TPB, TPB>>>(zvol, zprice, S, Vv);
}

// round 8
// speedup vs baseline: 1.3643x; 1.3643x over previous
#include <cuda_runtime.h>

// Heston Monte Carlo: 65536 paths x 512 steps.
// Inputs:  d_in[0] = Z_vol  [65536, 512, 2] f32 (only [:,:,0] used)
//          d_in[1] = Z_price[65536, 512]    f32
// Output:  d_out = S [65536,513] f32 followed by V [65536,513] f32
//
// Design: 64 paths per block (1 thread/path), steps processed in chunks of 16.
// Double-buffered smem tiles; next chunk's noise is prefetched into registers
// while the current chunk computes, so LDGs are in flight continuously.

#define NSTEPS   512
#define NP1      513
#define BATCH    65536
#define TPB      64
#define CHUNK    16
#define NCHUNKS  (NSTEPS / CHUNK)
#define SROW     (CHUNK + 1)   // smem row pitch (kills bank conflicts)

__global__ __launch_bounds__(TPB, 8) void heston_kernel(
    const float2* __restrict__ zvol,    // [BATCH][NSTEPS] float2
    const float*  __restrict__ zprice,  // [BATCH][NSTEPS]
    float* __restrict__ S_out,          // [BATCH][NP1]
    float* __restrict__ V_out)          // [BATCH][NP1]
{
    __shared__ float sA[2][TPB * SROW];  // zv tile -> S tile (in-place)
    __shared__ float sB[2][TPB * SROW];  // zp tile -> V tile (in-place)

    const int tid = threadIdx.x;
    const long long pbase  = (long long)blockIdx.x * TPB;
    const long long mypath = pbase + tid;

    // model constants
    const float dt       = 1.0f / 512.0f;
    const float sqrt_dt  = 0.04419417382415922f;     // sqrt(1/512)
    const float rho      = -0.7f;
    const float rho_perp = 0.7141428428542850f;      // sqrt(1-rho^2)
    const float V0f      = 0.055225f;                 // 0.235^2
    const float kth_dt   = 0.04f * dt;                // KAPPA*THETA*dt (KAPPA=1)
    const float two_sdt  = 2.0f * sqrt_dt;            // SIGMA_V * sqrt_dt

    // t = 0 column (tiny, uncoalesced, negligible)
    S_out[mypath * NP1] = 100.0f;
    V_out[mypath * NP1] = V0f;

    // ---- preload chunk 0 into stage 0 (coalesced: half-warp per path row) ----
    #pragma unroll
    for (int k = 0; k < CHUNK; k++) {
        const int i   = k * TPB + tid;
        const int row = i >> 4;          // path within block
        const int col = i & 15;          // step within chunk
        const long long g = (pbase + row) * (long long)NSTEPS + col;
        sA[0][row * SROW + col] = zvol[g].x;
        sB[0][row * SROW + col] = zprice[g];
    }
    __syncthreads();

    float V    = V0f;
    float logS = 0.0f;
    int   ping = 0;

    for (int ck = 0; ck < NCHUNKS; ck++) {
        const int cur = ping;
        const int nxt = ping ^ 1;
        const bool has_next = (ck + 1 < NCHUNKS);

        // ---- prefetch chunk ck+1 into registers (latency hidden by compute) ----
        float2 pzv[CHUNK];
        float  pzp[CHUNK];
        if (has_next) {
            const int t0n = (ck + 1) * CHUNK;
            #pragma unroll
            for (int k = 0; k < CHUNK; k++) {
                const int i   = k * TPB + tid;
                const int row = i >> 4;
                const int col = i & 15;
                const long long g = (pbase + row) * (long long)NSTEPS + t0n + col;
                pzv[k] = zvol[g];
                pzp[k] = zprice[g];
            }
        }

        // ---- compute: thread owns its path row; overwrite smem with S/V ----
        {
            float* myA = &sA[cur][tid * SROW];
            float* myB = &sB[cur][tid * SROW];
            #pragma unroll
            for (int c = 0; c < CHUNK; c++) {
                const float zv = myA[c];
                const float zp = myB[c];

                const float Vpos = fmaxf(V, 0.0f);
                const float sv   = sqrtf(Vpos);
                float Vnext = fmaf(two_sdt * zv, sv, fmaf(-dt, Vpos, V + kth_dt));
                Vnext = fmaxf(Vnext, 0.0f);

                const float dB = sqrt_dt * fmaf(rho, zv, rho_perp * zp);
                logS = fmaf(sv, dB, fmaf(-0.5f * dt, Vpos, logS));

                myA[c] = 100.0f * __expf(logS);   // S
                myB[c] = Vnext;                   // V
                V = Vnext;
            }
        }
        __syncthreads();   // compute writes visible to cooperative store

        // ---- cooperative coalesced store of chunk ck ----
        {
            const int t0 = ck * CHUNK;
            #pragma unroll
            for (int k = 0; k < CHUNK; k++) {
                const int i   = k * TPB + tid;
                const int row = i >> 4;
                const int col = i & 15;
                const long long o = (pbase + row) * (long long)NP1 + (t0 + 1 + col);
                S_out[o] = sA[cur][row * SROW + col];
                V_out[o] = sB[cur][row * SROW + col];
            }
        }

        // ---- stage the prefetched chunk into the other buffer ----
        if (has_next) {
            #pragma unroll
            for (int k = 0; k < CHUNK; k++) {
                const int i   = k * TPB + tid;
                const int row = i >> 4;
                const int col = i & 15;
                sA[nxt][row * SROW + col] = pzv[k].x;
                sB[nxt][row * SROW + col] = pzp[k];
            }
        }
        __syncthreads();   // staged data visible before next compute
        ping ^= 1;
    }
}

extern "C" void kernel_launch(void* const* d_in, const int* in_sizes, int n_in,
                              void* d_out, int out_size) {
    const float2* zvol   = (const float2*)d_in[0];
    const float*  zprice = (const float*) d_in[1];
    float* S  = (float*)d_out;
    float* Vv = S + (size_t)BATCH * NP1;

    heston_kernel<<<BATCH / TPB, TPB>>>(zvol, zprice, S, Vv);
}